// round 1
// baseline (speedup 1.0000x reference)
#include <cuda_runtime.h>
#include <cuda_bf16.h>

// Problem constants
#define BB   16
#define NTOK 577
#define CH   768
#define HH   12
#define DD   64
#define C3   (3 * CH)          // 2304
#define MROW (BB * NTOK)       // 9232
#define NBH  (BB * HH)         // 192
#define NN2  (NTOK * NTOK)     // 332929

// ---------------------------------------------------------------------------
// Scratch (static device globals; no runtime allocation allowed)
// ---------------------------------------------------------------------------
__device__ float g_qkv[(size_t)MROW * C3];          // [b,n,3,h,d]   ~85 MB
__device__ float g_S  [(size_t)NBH  * NN2];         // [b,h,n,m]     ~256 MB
__device__ float g_P2 [(size_t)NBH  * NN2];         // [b,g,n,m]     ~256 MB
__device__ float g_tmp[(size_t)MROW * CH];          // [b,n,h,d]     ~28 MB

// ---------------------------------------------------------------------------
// Generic register-tiled SGEMM.
//   C[m,n] = alpha * sum_k A(m,k) * B(k,n)  (+ bias[n])
//   A is always K-major: A[m*lda + k]
//   TRANSB=true : B K-major: B[n*ldb + k]   (NT form)
//   TRANSB=false: B N-major: B[k*ldb + n]   (NN form)
// Batched over gridDim.z = Bdim*Hdim with independent strides.
// ---------------------------------------------------------------------------
template<int BM, int BN, int BK, int TM, int TN, bool TRANSB>
__global__ __launch_bounds__((BM/TM)*(BN/TN))
void sgemm_kernel(const float* __restrict__ A, const float* __restrict__ B,
                  float* __restrict__ C, const float* __restrict__ bias,
                  int M, int Nn, int K, int lda, int ldb, int ldc, float alpha,
                  int Hdim,
                  long long sAb, long long sAh,
                  long long sBb, long long sBh,
                  long long sCb, long long sCh)
{
    const int z  = blockIdx.z;
    const int bb = z / Hdim;
    const int hh = z % Hdim;
    A += bb * sAb + hh * sAh;
    B += bb * sBb + hh * sBh;
    C += bb * sCb + hh * sCh;

    __shared__ float As[BK][BM];
    __shared__ float Bs[BK][BN];

    const int m0  = blockIdx.y * BM;
    const int n0  = blockIdx.x * BN;
    const int tid = threadIdx.x;
    constexpr int TNUM = (BM/TM) * (BN/TN);
    const int tn0 = (tid % (BN/TN)) * TN;
    const int tm0 = (tid / (BN/TN)) * TM;

    float acc[TM][TN];
#pragma unroll
    for (int i = 0; i < TM; i++)
#pragma unroll
        for (int j = 0; j < TN; j++) acc[i][j] = 0.f;

    for (int k0 = 0; k0 < K; k0 += BK) {
        // Load A tile (coalesced: consecutive tid -> consecutive k)
#pragma unroll
        for (int i = tid; i < BM * BK; i += TNUM) {
            int kk = i % BK, mm = i / BK;
            int gm = m0 + mm, gk = k0 + kk;
            As[kk][mm] = (gm < M && gk < K) ? A[(long long)gm * lda + gk] : 0.f;
        }
        // Load B tile
        if (TRANSB) {
#pragma unroll
            for (int i = tid; i < BN * BK; i += TNUM) {
                int kk = i % BK, nn = i / BK;
                int gn = n0 + nn, gk = k0 + kk;
                Bs[kk][nn] = (gn < Nn && gk < K) ? B[(long long)gn * ldb + gk] : 0.f;
            }
        } else {
#pragma unroll
            for (int i = tid; i < BN * BK; i += TNUM) {
                int nn = i % BN, kk = i / BN;
                int gn = n0 + nn, gk = k0 + kk;
                Bs[kk][nn] = (gn < Nn && gk < K) ? B[(long long)gk * ldb + gn] : 0.f;
            }
        }
        __syncthreads();

#pragma unroll
        for (int kk = 0; kk < BK; kk++) {
            float ra[TM], rb[TN];
#pragma unroll
            for (int i = 0; i < TM; i++) ra[i] = As[kk][tm0 + i];
#pragma unroll
            for (int j = 0; j < TN; j++) rb[j] = Bs[kk][tn0 + j];
#pragma unroll
            for (int i = 0; i < TM; i++)
#pragma unroll
                for (int j = 0; j < TN; j++)
                    acc[i][j] += ra[i] * rb[j];
        }
        __syncthreads();
    }

#pragma unroll
    for (int i = 0; i < TM; i++) {
        int gm = m0 + tm0 + i;
        if (gm >= M) continue;
#pragma unroll
        for (int j = 0; j < TN; j++) {
            int gn = n0 + tn0 + j;
            if (gn >= Nn) continue;
            float v = acc[i][j] * alpha;
            if (bias) v += bias[gn];
            C[(long long)gm * ldc + gn] = v;
        }
    }
}

// ---------------------------------------------------------------------------
// Fused talking-heads: Wpre mix -> softmax over m -> Wpost mix.
// One block per (b, n). All 12 heads of one query row live in shared memory.
//   In : S [b,h,n,m] logits (already scaled)
//   Out: P2[b,g,n,m]
// ---------------------------------------------------------------------------
#define ROWPAD 578   // row stride in smem floats

__global__ __launch_bounds__(256)
void mix_softmax_kernel(const float* __restrict__ S,
                        const float* __restrict__ Wpre,
                        const float* __restrict__ Wpost,
                        float* __restrict__ P2)
{
    extern __shared__ float smem[];
    float* Ssh = smem;                     // [12][ROWPAD]
    float* Tsh = smem + HH * ROWPAD;       // [12][ROWPAD]
    __shared__ float wpre_s[HH * HH];
    __shared__ float wpost_s[HH * HH];

    const int bn = blockIdx.x;
    const int b  = bn / NTOK;
    const int n  = bn % NTOK;
    const int tid = threadIdx.x;

    if (tid < HH * HH) {
        wpre_s[tid]  = Wpre[tid];
        wpost_s[tid] = Wpost[tid];
    }

    // Load all 12 head rows of logits
    for (int i = tid; i < HH * NTOK; i += blockDim.x) {
        int h = i / NTOK, m = i % NTOK;
        Ssh[h * ROWPAD + m] =
            S[((long long)(b * HH + h) * NTOK + n) * NTOK + m];
    }
    __syncthreads();

    // Pre-mix: T[g][m] = sum_h Wpre[g,h] * S[h][m]
    for (int i = tid; i < HH * NTOK; i += blockDim.x) {
        int g = i / NTOK, m = i % NTOK;
        float accv = 0.f;
#pragma unroll
        for (int h = 0; h < HH; h++)
            accv += wpre_s[g * HH + h] * Ssh[h * ROWPAD + m];
        Tsh[g * ROWPAD + m] = accv;
    }
    __syncthreads();

    // Softmax per mixed head row (warp per row; 8 warps cover 12 rows)
    const int warp = tid / 32, lane = tid % 32;
    for (int g = warp; g < HH; g += 8) {
        float* row = Tsh + g * ROWPAD;
        float mx = -1e30f;
        for (int m = lane; m < NTOK; m += 32) mx = fmaxf(mx, row[m]);
#pragma unroll
        for (int o = 16; o > 0; o >>= 1)
            mx = fmaxf(mx, __shfl_xor_sync(0xffffffffu, mx, o));
        float s = 0.f;
        for (int m = lane; m < NTOK; m += 32) {
            float e = __expf(row[m] - mx);
            row[m] = e;
            s += e;
        }
#pragma unroll
        for (int o = 16; o > 0; o >>= 1)
            s += __shfl_xor_sync(0xffffffffu, s, o);
        float inv = 1.f / s;
        for (int m = lane; m < NTOK; m += 32) row[m] *= inv;
    }
    __syncthreads();

    // Post-mix + store: P2[g][m] = sum_h Wpost[g,h] * softmaxed[h][m]
    for (int i = tid; i < HH * NTOK; i += blockDim.x) {
        int g = i / NTOK, m = i % NTOK;
        float accv = 0.f;
#pragma unroll
        for (int h = 0; h < HH; h++)
            accv += wpost_s[g * HH + h] * Tsh[h * ROWPAD + m];
        P2[((long long)(b * HH + g) * NTOK + n) * NTOK + m] = accv;
    }
}

// ---------------------------------------------------------------------------
// Launch
// ---------------------------------------------------------------------------
extern "C" void kernel_launch(void* const* d_in, const int* in_sizes, int n_in,
                              void* d_out, int out_size)
{
    const float* x     = (const float*)d_in[0];   // [16,577,768]
    const float* Wqkv  = (const float*)d_in[1];   // [2304,768]
    const float* Wproj = (const float*)d_in[2];   // [768,768]
    const float* bproj = (const float*)d_in[3];   // [768]
    const float* Wpre  = (const float*)d_in[4];   // [12,12]
    const float* Wpost = (const float*)d_in[5];   // [12,12]
    float* out = (float*)d_out;                   // [16,577,768]

    float *qkv, *S, *P2, *tmp;
    cudaGetSymbolAddress((void**)&qkv, g_qkv);
    cudaGetSymbolAddress((void**)&S,   g_S);
    cudaGetSymbolAddress((void**)&P2,  g_P2);
    cudaGetSymbolAddress((void**)&tmp, g_tmp);

    // 1) QKV GEMM: qkv = x @ Wqkv^T     [9232 x 2304], K=768, NT
    {
        dim3 grid((C3 + 127) / 128, (MROW + 127) / 128, 1);
        sgemm_kernel<128,128,8,8,8,true><<<grid, 256>>>(
            x, Wqkv, qkv, nullptr,
            MROW, C3, CH, CH, CH, C3, 1.0f,
            1, 0, 0, 0, 0, 0, 0);
    }

    // 2) Scores: S[b,h,n,m] = 1/8 * q.k   (batched 192, M=N=577, K=64, NT)
    {
        dim3 grid((NTOK + 127) / 128, (NTOK + 127) / 128, NBH);
        sgemm_kernel<128,128,8,8,8,true><<<grid, 256>>>(
            qkv,                 // q: offset h*64 within row
            qkv + HH * DD,       // k: +768
            S, nullptr,
            NTOK, NTOK, DD,
            C3, C3, NTOK, 0.125f,
            HH,
            (long long)NTOK * C3, DD,          // A batch strides (b, h)
            (long long)NTOK * C3, DD,          // B batch strides
            (long long)HH * NN2, NN2);         // C batch strides
    }

    // 3) Fused Wpre-mix -> softmax -> Wpost-mix
    {
        size_t shbytes = (size_t)2 * HH * ROWPAD * sizeof(float); // ~55.5 KB
        cudaFuncSetAttribute(mix_softmax_kernel,
                             cudaFuncAttributeMaxDynamicSharedMemorySize,
                             (int)shbytes);
        mix_softmax_kernel<<<MROW, 256, shbytes>>>(S, Wpre, Wpost, P2);
    }

    // 4) AV: tmp[b,n,h,d] = sum_m P2[b,h,n,m] * v[b,m,h,d]
    //    batched 192, M=577, N=64, K=577, NN form
    {
        dim3 grid(1, (NTOK + 127) / 128, NBH);
        sgemm_kernel<128,64,8,8,4,false><<<grid, 256>>>(
            P2,
            qkv + 2 * HH * DD,   // v: +1536
            tmp, nullptr,
            NTOK, DD, NTOK,
            NTOK, C3, CH, 1.0f,
            HH,
            (long long)HH * NN2, NN2,          // A batch strides
            (long long)NTOK * C3, DD,          // B batch strides
            (long long)NTOK * CH, DD);         // C batch strides
    }

    // 5) Projection: out = tmp @ Wproj^T + bproj   [9232 x 768], K=768, NT
    {
        dim3 grid((CH + 127) / 128, (MROW + 127) / 128, 1);
        sgemm_kernel<128,128,8,8,8,true><<<grid, 256>>>(
            tmp, Wproj, out, bproj,
            MROW, CH, CH, CH, CH, CH, 1.0f,
            1, 0, 0, 0, 0, 0, 0);
    }
}

// round 2
// speedup vs baseline: 2.7727x; 2.7727x over previous
#include <cuda_runtime.h>
#include <cuda_bf16.h>
#include <cstdint>

// Problem constants
#define BB   16
#define NTOK 577
#define CH   768
#define HH   12
#define DD   64
#define C3   (3 * CH)          // 2304
#define MROW (BB * NTOK)       // 9232
#define NBH  (BB * HH)         // 192

#define LD_S  580              // S row stride (mult of 4)
#define LD_P  608              // P2 row stride (mult of 32: K-pad for AV GEMM)

// ---------------------------------------------------------------------------
// Scratch (static device globals; zero-initialized at load; no runtime alloc)
// ---------------------------------------------------------------------------
__device__ __align__(16) float g_qkv[(size_t)MROW * C3];             // ~85 MB
__device__ __align__(16) float g_S  [(size_t)NBH * NTOK * LD_S];     // ~257 MB
__device__ __align__(16) float g_P2 [(size_t)NBH * NTOK * LD_P];     // ~269 MB
__device__ __align__(16) float g_vT [(size_t)NBH * DD * LD_P];       // ~30 MB
__device__ __align__(16) float g_tmp[(size_t)MROW * CH];             // ~28 MB

__device__ __forceinline__ uint32_t f2tf32(float f) {
    uint32_t r;
    asm("cvt.rna.tf32.f32 %0, %1;" : "=r"(r) : "f"(f));
    return r;
}

// ---------------------------------------------------------------------------
// Tensor-core NT GEMM (tf32 mma.sync, fp32 accumulate)
//   C[m,n] = alpha * sum_k A[m*lda+k] * B[n*ldb+k]  (+ bias[n])
// 256 threads, warps 2(M) x 4(N). BK=32. K must be a multiple of 32.
// Batched over gridDim.z (Hdim sub-batches with separate strides).
// ---------------------------------------------------------------------------
template<int BM, int BN>
__global__ __launch_bounds__(256, 2)
void tc_gemm_nt(const float* __restrict__ A, const float* __restrict__ B,
                float* __restrict__ C, const float* __restrict__ bias,
                int M, int Nn, int K, int lda, int ldb, int ldc, float alpha,
                int Hdim,
                long long sAb, long long sAh,
                long long sBb, long long sBh,
                long long sCb, long long sCh)
{
    constexpr int BK  = 32;
    constexpr int LW  = BK + 4;           // padded smem row (36)
    constexpr int MI  = BM / 2 / 16;      // m16 frags per warp
    constexpr int NJ  = BN / 4 / 8;       // n8 frags per warp

    __shared__ uint32_t As[BM * LW];
    __shared__ uint32_t Bs[BN * LW];

    const int z  = blockIdx.z;
    const int bb = z / Hdim;
    const int hh = z % Hdim;
    A += bb * sAb + hh * sAh;
    B += bb * sBb + hh * sBh;
    C += bb * sCb + hh * sCh;

    const int m0   = blockIdx.y * BM;
    const int n0   = blockIdx.x * BN;
    const int tid  = threadIdx.x;
    const int wid  = tid >> 5;
    const int lane = tid & 31;
    const int g    = lane >> 2;           // group id (0..7)
    const int t    = lane & 3;            // thread-in-group
    const int wm   = (wid >> 2) * (BM / 2);
    const int wn   = (wid & 3) * (BN / 4);

    const int lr = tid >> 3;              // 0..31 (smem load row)
    const int lc = (tid & 7) * 4;         // 0..28 (smem load col)

    float acc[MI][NJ][4];
#pragma unroll
    for (int i = 0; i < MI; i++)
#pragma unroll
        for (int j = 0; j < NJ; j++)
#pragma unroll
            for (int q = 0; q < 4; q++) acc[i][j][q] = 0.f;

    for (int k0 = 0; k0 < K; k0 += BK) {
        // ---- load A tile ----
#pragma unroll
        for (int r = lr; r < BM; r += 32) {
            int gm = m0 + r;
            float4 v = make_float4(0.f, 0.f, 0.f, 0.f);
            if (gm < M)
                v = *reinterpret_cast<const float4*>(A + (long long)gm * lda + k0 + lc);
            uint4 u;
            u.x = f2tf32(v.x); u.y = f2tf32(v.y);
            u.z = f2tf32(v.z); u.w = f2tf32(v.w);
            *reinterpret_cast<uint4*>(&As[r * LW + lc]) = u;
        }
        // ---- load B tile ----
#pragma unroll
        for (int r = lr; r < BN; r += 32) {
            int gn = n0 + r;
            float4 v = make_float4(0.f, 0.f, 0.f, 0.f);
            if (gn < Nn)
                v = *reinterpret_cast<const float4*>(B + (long long)gn * ldb + k0 + lc);
            uint4 u;
            u.x = f2tf32(v.x); u.y = f2tf32(v.y);
            u.z = f2tf32(v.z); u.w = f2tf32(v.w);
            *reinterpret_cast<uint4*>(&Bs[r * LW + lc]) = u;
        }
        __syncthreads();

#pragma unroll
        for (int s = 0; s < 4; s++) {
            const int kb = s * 8;
            uint32_t af[MI][4];
#pragma unroll
            for (int i = 0; i < MI; i++) {
                const uint32_t* p0 = &As[(wm + i * 16 + g)     * LW + kb + t];
                const uint32_t* p1 = &As[(wm + i * 16 + g + 8) * LW + kb + t];
                af[i][0] = p0[0]; af[i][2] = p0[4];
                af[i][1] = p1[0]; af[i][3] = p1[4];
            }
            uint32_t bf[NJ][2];
#pragma unroll
            for (int j = 0; j < NJ; j++) {
                const uint32_t* p = &Bs[(wn + j * 8 + g) * LW + kb + t];
                bf[j][0] = p[0]; bf[j][1] = p[4];
            }
#pragma unroll
            for (int i = 0; i < MI; i++)
#pragma unroll
                for (int j = 0; j < NJ; j++) {
                    asm volatile(
                        "mma.sync.aligned.m16n8k8.row.col.f32.tf32.tf32.f32 "
                        "{%0,%1,%2,%3}, {%4,%5,%6,%7}, {%8,%9}, {%0,%1,%2,%3};"
                        : "+f"(acc[i][j][0]), "+f"(acc[i][j][1]),
                          "+f"(acc[i][j][2]), "+f"(acc[i][j][3])
                        : "r"(af[i][0]), "r"(af[i][1]), "r"(af[i][2]), "r"(af[i][3]),
                          "r"(bf[j][0]), "r"(bf[j][1]));
                }
        }
        __syncthreads();
    }

    // ---- epilogue ----
#pragma unroll
    for (int i = 0; i < MI; i++) {
        int gm0 = m0 + wm + i * 16 + g;
        int gm1 = gm0 + 8;
#pragma unroll
        for (int j = 0; j < NJ; j++) {
            int gn = n0 + wn + j * 8 + 2 * t;
            float b0 = 0.f, b1 = 0.f;
            if (bias) {
                if (gn < Nn)     b0 = bias[gn];
                if (gn + 1 < Nn) b1 = bias[gn + 1];
            }
            float c0 = acc[i][j][0] * alpha + b0;
            float c1 = acc[i][j][1] * alpha + b1;
            float c2 = acc[i][j][2] * alpha + b0;
            float c3 = acc[i][j][3] * alpha + b1;
            if (gm0 < M) {
                if (gn + 1 < Nn)
                    *reinterpret_cast<float2*>(C + (long long)gm0 * ldc + gn) = make_float2(c0, c1);
                else if (gn < Nn)
                    C[(long long)gm0 * ldc + gn] = c0;
            }
            if (gm1 < M) {
                if (gn + 1 < Nn)
                    *reinterpret_cast<float2*>(C + (long long)gm1 * ldc + gn) = make_float2(c2, c3);
                else if (gn < Nn)
                    C[(long long)gm1 * ldc + gn] = c2;
            }
        }
    }
}

// ---------------------------------------------------------------------------
// Transpose V: qkv[b,m, 2, h, d] -> vT[b,h, d, m] (ld = LD_P, pad stays 0)
// ---------------------------------------------------------------------------
__global__ __launch_bounds__(256)
void transpose_v_kernel(const float* __restrict__ qkv, float* __restrict__ vT)
{
    __shared__ float tile[32][33];
    const int dBase = (blockIdx.x & 1) * 32;       // 0 or 32
    const int mBase = blockIdx.y * 32;
    const int bh    = blockIdx.z;
    const int b     = bh / HH;
    const int h     = bh % HH;
    const int tx = threadIdx.x & 31;
    const int ty = threadIdx.x >> 5;               // 0..7

    const float* src = qkv + (long long)b * NTOK * C3 + 2 * CH + h * DD;
#pragma unroll
    for (int i = 0; i < 4; i++) {
        int m = mBase + ty + i * 8;
        if (m < NTOK)
            tile[ty + i * 8][tx] = src[(long long)m * C3 + dBase + tx];
    }
    __syncthreads();

    float* dst = vT + (long long)bh * DD * LD_P;
#pragma unroll
    for (int i = 0; i < 4; i++) {
        int d = dBase + ty + i * 8;
        int m = mBase + tx;
        if (m < NTOK)
            dst[(long long)d * LD_P + m] = tile[tx][ty + i * 8];
    }
}

// ---------------------------------------------------------------------------
// Fused talking-heads: Wpre mix -> softmax over m -> Wpost mix.
// One block per (b, n). In: S[b,h,n,:] (ld LD_S). Out: P2[b,g,n,:] (ld LD_P,
// cols 577..607 zeroed for the K-padded AV GEMM).
// ---------------------------------------------------------------------------
#define ROWPAD 578

__global__ __launch_bounds__(256)
void mix_softmax_kernel(const float* __restrict__ S,
                        const float* __restrict__ Wpre,
                        const float* __restrict__ Wpost,
                        float* __restrict__ P2)
{
    extern __shared__ float smem[];
    float* Ssh = smem;                 // [12][ROWPAD]
    float* Tsh = smem + HH * ROWPAD;   // [12][ROWPAD]
    __shared__ float wpre_s[HH * HH];
    __shared__ float wpost_s[HH * HH];

    const int bn = blockIdx.x;
    const int b  = bn / NTOK;
    const int n  = bn % NTOK;
    const int tid = threadIdx.x;

    if (tid < HH * HH) {
        wpre_s[tid]  = Wpre[tid];
        wpost_s[tid] = Wpost[tid];
    }

    for (int i = tid; i < HH * NTOK; i += blockDim.x) {
        int h = i / NTOK, m = i % NTOK;
        Ssh[h * ROWPAD + m] =
            S[((long long)(b * HH + h) * NTOK + n) * LD_S + m];
    }
    __syncthreads();

    for (int i = tid; i < HH * NTOK; i += blockDim.x) {
        int gg = i / NTOK, m = i % NTOK;
        float accv = 0.f;
#pragma unroll
        for (int h = 0; h < HH; h++)
            accv += wpre_s[gg * HH + h] * Ssh[h * ROWPAD + m];
        Tsh[gg * ROWPAD + m] = accv;
    }
    __syncthreads();

    const int warp = tid / 32, lane = tid % 32;
    for (int gg = warp; gg < HH; gg += 8) {
        float* row = Tsh + gg * ROWPAD;
        float mx = -1e30f;
        for (int m = lane; m < NTOK; m += 32) mx = fmaxf(mx, row[m]);
#pragma unroll
        for (int o = 16; o > 0; o >>= 1)
            mx = fmaxf(mx, __shfl_xor_sync(0xffffffffu, mx, o));
        float s = 0.f;
        for (int m = lane; m < NTOK; m += 32) {
            float e = __expf(row[m] - mx);
            row[m] = e;
            s += e;
        }
#pragma unroll
        for (int o = 16; o > 0; o >>= 1)
            s += __shfl_xor_sync(0xffffffffu, s, o);
        float inv = 1.f / s;
        for (int m = lane; m < NTOK; m += 32) row[m] *= inv;
    }
    __syncthreads();

    for (int i = tid; i < HH * NTOK; i += blockDim.x) {
        int gg = i / NTOK, m = i % NTOK;
        float accv = 0.f;
#pragma unroll
        for (int h = 0; h < HH; h++)
            accv += wpost_s[gg * HH + h] * Tsh[h * ROWPAD + m];
        P2[((long long)(b * HH + gg) * NTOK + n) * LD_P + m] = accv;
    }
    // zero the K-pad columns (577..607) for the padded AV GEMM
    for (int i = tid; i < HH * (LD_P - NTOK); i += blockDim.x) {
        int gg = i / (LD_P - NTOK), m = NTOK + i % (LD_P - NTOK);
        P2[((long long)(b * HH + gg) * NTOK + n) * LD_P + m] = 0.f;
    }
}

// ---------------------------------------------------------------------------
// Launch
// ---------------------------------------------------------------------------
extern "C" void kernel_launch(void* const* d_in, const int* in_sizes, int n_in,
                              void* d_out, int out_size)
{
    const float* x     = (const float*)d_in[0];   // [16,577,768]
    const float* Wqkv  = (const float*)d_in[1];   // [2304,768]
    const float* Wproj = (const float*)d_in[2];   // [768,768]
    const float* bproj = (const float*)d_in[3];   // [768]
    const float* Wpre  = (const float*)d_in[4];   // [12,12]
    const float* Wpost = (const float*)d_in[5];   // [12,12]
    float* out = (float*)d_out;                   // [16,577,768]

    float *qkv, *S, *P2, *vT, *tmp;
    cudaGetSymbolAddress((void**)&qkv, g_qkv);
    cudaGetSymbolAddress((void**)&S,   g_S);
    cudaGetSymbolAddress((void**)&P2,  g_P2);
    cudaGetSymbolAddress((void**)&vT,  g_vT);
    cudaGetSymbolAddress((void**)&tmp, g_tmp);

    // 1) QKV GEMM: qkv = x @ Wqkv^T   [9232 x 2304], K=768
    {
        dim3 grid(C3 / 128, (MROW + 127) / 128, 1);
        tc_gemm_nt<128, 128><<<grid, 256>>>(
            x, Wqkv, qkv, nullptr,
            MROW, C3, CH, CH, CH, C3, 1.0f,
            1, 0, 0, 0, 0, 0, 0);
    }

    // 1.5) Transpose V -> vT[b,h,d,m] (ld = LD_P; pad cols stay 0)
    {
        dim3 grid(2, (NTOK + 31) / 32, NBH);
        transpose_v_kernel<<<grid, 256>>>(qkv, vT);
    }

    // 2) Scores: S = 1/8 * q @ k^T   (batched 192, M=N=577, K=64)
    {
        dim3 grid((NTOK + 127) / 128, (NTOK + 127) / 128, NBH);
        tc_gemm_nt<128, 128><<<grid, 256>>>(
            qkv,            // q (offset h*64 via sAh)
            qkv + CH,       // k
            S, nullptr,
            NTOK, NTOK, DD,
            C3, C3, LD_S, 0.125f,
            HH,
            (long long)NTOK * C3, DD,
            (long long)NTOK * C3, DD,
            (long long)HH * NTOK * LD_S, (long long)NTOK * LD_S);
    }

    // 3) Fused Wpre-mix -> softmax -> Wpost-mix
    {
        size_t shbytes = (size_t)2 * HH * ROWPAD * sizeof(float);
        cudaFuncSetAttribute(mix_softmax_kernel,
                             cudaFuncAttributeMaxDynamicSharedMemorySize,
                             (int)shbytes);
        mix_softmax_kernel<<<MROW, 256, shbytes>>>(S, Wpre, Wpost, P2);
    }

    // 4) AV: tmp[b,n,h,d] = P2[b,h,n,:] @ vT[b,h,:,:]^T  (K padded to 608)
    {
        dim3 grid(1, (NTOK + 127) / 128, NBH);
        tc_gemm_nt<128, 64><<<grid, 256>>>(
            P2, vT, tmp, nullptr,
            NTOK, DD, LD_P,
            LD_P, LD_P, CH, 1.0f,
            HH,
            (long long)HH * NTOK * LD_P, (long long)NTOK * LD_P,
            (long long)HH * DD * LD_P,   (long long)DD * LD_P,
            (long long)NTOK * CH,        DD);
    }

    // 5) Projection: out = tmp @ Wproj^T + bproj   [9232 x 768], K=768
    {
        dim3 grid(CH / 128, (MROW + 127) / 128, 1);
        tc_gemm_nt<128, 128><<<grid, 256>>>(
            tmp, Wproj, out, bproj,
            MROW, CH, CH, CH, CH, CH, 1.0f,
            1, 0, 0, 0, 0, 0, 0);
    }
}

// round 3
// speedup vs baseline: 3.8991x; 1.4062x over previous
#include <cuda_runtime.h>
#include <cuda_bf16.h>
#include <cstdint>

// Problem constants
#define BB   16
#define NTOK 577
#define CH   768
#define HH   12
#define DD   64
#define C3   (3 * CH)          // 2304
#define MROW (BB * NTOK)       // 9232
#define NBH  (BB * HH)         // 192

#define LD_S  580              // S row stride
#define LD_P  608              // P2 row stride (mult of 32: K-pad for AV GEMM)

// ---------------------------------------------------------------------------
// Scratch (static device globals; zero-initialized; no runtime alloc)
// ---------------------------------------------------------------------------
__device__ __align__(16) float g_qkv[(size_t)MROW * C3];             // ~85 MB
__device__ __align__(16) float g_S  [(size_t)NBH * NTOK * LD_S];     // ~257 MB
__device__ __align__(16) float g_P2 [(size_t)NBH * NTOK * LD_P];     // ~269 MB
__device__ __align__(16) float g_vT [(size_t)NBH * DD * LD_P];       // ~30 MB
__device__ __align__(16) float g_tmp[(size_t)MROW * CH];             // ~28 MB
__device__ __align__(16) float g_xr   [(size_t)MROW * CH];           // ~28 MB
__device__ __align__(16) float g_wqkvr[(size_t)C3 * CH];             // ~7 MB
__device__ __align__(16) float g_wprojr[(size_t)CH * CH];            // ~2.4 MB

__device__ __forceinline__ uint32_t f2tf32(float f) {
    uint32_t r;
    asm("cvt.rna.tf32.f32 %0, %1;" : "=r"(r) : "f"(f));
    return r;
}
__device__ __forceinline__ float rndf(float f) { return __uint_as_float(f2tf32(f)); }

// f32x2 helpers
__device__ __forceinline__ unsigned long long pk2(float lo, float hi) {
    unsigned long long u;
    asm("mov.b64 %0, {%1, %2};" : "=l"(u) : "r"(__float_as_uint(lo)), "r"(__float_as_uint(hi)));
    return u;
}
__device__ __forceinline__ void upk2(unsigned long long u, float& lo, float& hi) {
    uint32_t a, b;
    asm("mov.b64 {%0, %1}, %2;" : "=r"(a), "=r"(b) : "l"(u));
    lo = __uint_as_float(a); hi = __uint_as_float(b);
}
__device__ __forceinline__ unsigned long long fma2(unsigned long long a,
                                                   unsigned long long b,
                                                   unsigned long long c) {
    unsigned long long d;
    asm("fma.rn.f32x2 %0, %1, %2, %3;" : "=l"(d) : "l"(a), "l"(b), "l"(c));
    return d;
}
__device__ __forceinline__ unsigned long long mul2(unsigned long long a,
                                                   unsigned long long b) {
    unsigned long long d;
    asm("mul.rn.f32x2 %0, %1, %2;" : "=l"(d) : "l"(a), "l"(b));
    return d;
}

// ---------------------------------------------------------------------------
// Elementwise tf32-round copy (float4 vectorized, n % 4 == 0)
// ---------------------------------------------------------------------------
__global__ __launch_bounds__(256)
void round_copy_kernel(const float* __restrict__ in, float* __restrict__ out, int n4)
{
    int i = blockIdx.x * 256 + threadIdx.x;
    int stride = gridDim.x * 256;
    for (; i < n4; i += stride) {
        float4 v = reinterpret_cast<const float4*>(in)[i];
        v.x = rndf(v.x); v.y = rndf(v.y); v.z = rndf(v.z); v.w = rndf(v.w);
        reinterpret_cast<float4*>(out)[i] = v;
    }
}

// ---------------------------------------------------------------------------
// Tensor-core NT GEMM (tf32 mma.sync, fp32 accumulate), cp.async 2-stage.
// Inputs MUST already be tf32-rounded fp32.
//   C[m,n] = alpha * sum_k A[m*lda+k] * B[n*ldb+k]  (+ bias[n])
// 256 threads, warps 2(M) x 4(N). BK=32, K % 32 == 0.
// ---------------------------------------------------------------------------
__device__ __forceinline__ void cp16(uint32_t saddr, const float* g, bool v) {
    asm volatile("cp.async.cg.shared.global [%0], [%1], 16, %2;"
                 :: "r"(saddr), "l"(g), "r"(v ? 16 : 0));
}

template<int BM, int BN, bool ROUND>
__global__ __launch_bounds__(256, 2)
void tc_gemm_nt(const float* __restrict__ A, const float* __restrict__ B,
                float* __restrict__ C, const float* __restrict__ bias,
                int M, int Nn, int K, int lda, int ldb, int ldc, float alpha,
                int Hdim,
                long long sAb, long long sAh,
                long long sBb, long long sBh,
                long long sCb, long long sCh)
{
    constexpr int BK = 32;
    constexpr int LW = BK + 4;            // padded smem row (36)
    constexpr int MI = BM / 2 / 16;
    constexpr int NJ = BN / 4 / 8;

    extern __shared__ uint32_t sm[];
    uint32_t* Asm = sm;                   // [2][BM*LW]
    uint32_t* Bsm = sm + 2 * BM * LW;     // [2][BN*LW]

    const int z  = blockIdx.z;
    const int bb = z / Hdim;
    const int hh = z % Hdim;
    A += bb * sAb + hh * sAh;
    B += bb * sBb + hh * sBh;
    C += bb * sCb + hh * sCh;

    const int m0   = blockIdx.y * BM;
    const int n0   = blockIdx.x * BN;
    const int tid  = threadIdx.x;
    const int wid  = tid >> 5;
    const int lane = tid & 31;
    const int g    = lane >> 2;
    const int t    = lane & 3;
    const int wm   = (wid >> 2) * (BM / 2);
    const int wn   = (wid & 3) * (BN / 4);

    const int lr = tid >> 3;              // 0..31
    const int lc = (tid & 7) * 4;         // 0..28

    const uint32_t sA = (uint32_t)__cvta_generic_to_shared(Asm);
    const uint32_t sB = (uint32_t)__cvta_generic_to_shared(Bsm);

    float acc[MI][NJ][4];
#pragma unroll
    for (int i = 0; i < MI; i++)
#pragma unroll
        for (int j = 0; j < NJ; j++)
#pragma unroll
            for (int q = 0; q < 4; q++) acc[i][j][q] = 0.f;

    const int niter = K / BK;

    // issue one stage's loads
    auto issue = [&](int k0, int st) {
#pragma unroll
        for (int q = 0; q < BM / 32; q++) {
            int r = lr + q * 32;
            int gm = m0 + r;
            bool v = gm < M;
            const float* gp = A + (long long)(v ? gm : 0) * lda + k0 + lc;
            cp16(sA + (uint32_t)(st * BM * LW + r * LW + lc) * 4, gp, v);
        }
#pragma unroll
        for (int q = 0; q < BN / 32; q++) {
            int r = lr + q * 32;
            int gn = n0 + r;
            bool v = gn < Nn;
            const float* gp = B + (long long)(v ? gn : 0) * ldb + k0 + lc;
            cp16(sB + (uint32_t)(st * BN * LW + r * LW + lc) * 4, gp, v);
        }
        asm volatile("cp.async.commit_group;" ::: "memory");
    };

    issue(0, 0);

    for (int it = 0; it < niter; it++) {
        if (it + 1 < niter) {
            issue((it + 1) * BK, (it + 1) & 1);
            asm volatile("cp.async.wait_group 1;" ::: "memory");
        } else {
            asm volatile("cp.async.wait_group 0;" ::: "memory");
        }
        __syncthreads();

        const uint32_t* Asb = Asm + (it & 1) * BM * LW;
        const uint32_t* Bsb = Bsm + (it & 1) * BN * LW;

#pragma unroll
        for (int s = 0; s < 4; s++) {
            const int kb = s * 8;
            uint32_t af[MI][4];
#pragma unroll
            for (int i = 0; i < MI; i++) {
                const uint32_t* p0 = &Asb[(wm + i * 16 + g)     * LW + kb + t];
                const uint32_t* p1 = &Asb[(wm + i * 16 + g + 8) * LW + kb + t];
                af[i][0] = p0[0]; af[i][2] = p0[4];
                af[i][1] = p1[0]; af[i][3] = p1[4];
            }
            uint32_t bf[NJ][2];
#pragma unroll
            for (int j = 0; j < NJ; j++) {
                const uint32_t* p = &Bsb[(wn + j * 8 + g) * LW + kb + t];
                bf[j][0] = p[0]; bf[j][1] = p[4];
            }
#pragma unroll
            for (int i = 0; i < MI; i++)
#pragma unroll
                for (int j = 0; j < NJ; j++) {
                    asm volatile(
                        "mma.sync.aligned.m16n8k8.row.col.f32.tf32.tf32.f32 "
                        "{%0,%1,%2,%3}, {%4,%5,%6,%7}, {%8,%9}, {%0,%1,%2,%3};"
                        : "+f"(acc[i][j][0]), "+f"(acc[i][j][1]),
                          "+f"(acc[i][j][2]), "+f"(acc[i][j][3])
                        : "r"(af[i][0]), "r"(af[i][1]), "r"(af[i][2]), "r"(af[i][3]),
                          "r"(bf[j][0]), "r"(bf[j][1]));
                }
        }
        __syncthreads();
    }

    // ---- epilogue ----
#pragma unroll
    for (int i = 0; i < MI; i++) {
        int gm0 = m0 + wm + i * 16 + g;
        int gm1 = gm0 + 8;
#pragma unroll
        for (int j = 0; j < NJ; j++) {
            int gn = n0 + wn + j * 8 + 2 * t;
            float b0 = 0.f, b1 = 0.f;
            if (bias) {
                if (gn < Nn)     b0 = bias[gn];
                if (gn + 1 < Nn) b1 = bias[gn + 1];
            }
            float c0 = acc[i][j][0] * alpha + b0;
            float c1 = acc[i][j][1] * alpha + b1;
            float c2 = acc[i][j][2] * alpha + b0;
            float c3 = acc[i][j][3] * alpha + b1;
            if (ROUND) { c0 = rndf(c0); c1 = rndf(c1); c2 = rndf(c2); c3 = rndf(c3); }
            if (gm0 < M) {
                if (gn + 1 < Nn)
                    *reinterpret_cast<float2*>(C + (long long)gm0 * ldc + gn) = make_float2(c0, c1);
                else if (gn < Nn)
                    C[(long long)gm0 * ldc + gn] = c0;
            }
            if (gm1 < M) {
                if (gn + 1 < Nn)
                    *reinterpret_cast<float2*>(C + (long long)gm1 * ldc + gn) = make_float2(c2, c3);
                else if (gn < Nn)
                    C[(long long)gm1 * ldc + gn] = c2;
            }
        }
    }
}

// ---------------------------------------------------------------------------
// Transpose V: qkv[b,m, 2, h, d] -> vT[b,h, d, m] (ld = LD_P, pad stays 0)
// ---------------------------------------------------------------------------
__global__ __launch_bounds__(256)
void transpose_v_kernel(const float* __restrict__ qkv, float* __restrict__ vT)
{
    __shared__ float tile[32][33];
    const int dBase = (blockIdx.x & 1) * 32;
    const int mBase = blockIdx.y * 32;
    const int bh    = blockIdx.z;
    const int b     = bh / HH;
    const int h     = bh % HH;
    const int tx = threadIdx.x & 31;
    const int ty = threadIdx.x >> 5;

    const float* src = qkv + (long long)b * NTOK * C3 + 2 * CH + h * DD;
#pragma unroll
    for (int i = 0; i < 4; i++) {
        int m = mBase + ty + i * 8;
        if (m < NTOK)
            tile[ty + i * 8][tx] = src[(long long)m * C3 + dBase + tx];
    }
    __syncthreads();

    float* dst = vT + (long long)bh * DD * LD_P;
#pragma unroll
    for (int i = 0; i < 4; i++) {
        int d = dBase + ty + i * 8;
        int m = mBase + tx;
        if (m < NTOK)
            dst[(long long)d * LD_P + m] = tile[tx][ty + i * 8];
    }
}

// ---------------------------------------------------------------------------
// Fused talking-heads (register version, f32x2):
// one block per (b,n); 320 threads; thread owns columns (m, m+320) packed.
//   In : S [b,h,n,:] (ld LD_S, raw fp32)
//   Out: P2[b,g,n,:] (ld LD_P, tf32-rounded; pad cols zeroed)
// ---------------------------------------------------------------------------
#define MIXT 320

__global__ __launch_bounds__(MIXT)
void mix_softmax_kernel(const float* __restrict__ S,
                        const float* __restrict__ Wpre,
                        const float* __restrict__ Wpost,
                        float* __restrict__ P2)
{
    __shared__ unsigned long long w2pre[HH * HH];
    __shared__ unsigned long long w2post[HH * HH];
    __shared__ float red[MIXT / 32][HH];
    __shared__ float smax[HH];
    __shared__ float sinv[HH];

    const int tid  = threadIdx.x;
    const int warp = tid >> 5;
    const int lane = tid & 31;
    const int bn = blockIdx.x;
    const int b  = bn / NTOK;
    const int n  = bn % NTOK;

    if (tid < HH * HH) {
        float wp = Wpre[tid];
        float wq = Wpost[tid];
        w2pre[tid]  = pk2(wp, wp);
        w2post[tid] = pk2(wq, wq);
    }
    __syncthreads();

    const float* Sb = S + ((long long)b * HH * NTOK + n) * LD_S;
    const int m0 = tid;
    const int m1 = tid + MIXT;
    const bool v1 = (m1 < NTOK);

    // Load all 12 head logits for both columns
    unsigned long long s2[HH];
#pragma unroll
    for (int h = 0; h < HH; h++) {
        const float* p = Sb + (long long)h * NTOK * LD_S;
        float lo = p[m0];
        float hi = v1 ? p[m1] : 0.f;
        s2[h] = pk2(lo, hi);
    }

    // Pre-mix (packed FFMA2)
    unsigned long long t2[HH];
#pragma unroll
    for (int gg = 0; gg < HH; gg++) {
        unsigned long long accv = 0ull;   // (+0.0f, +0.0f)
#pragma unroll
        for (int h = 0; h < HH; h++)
            accv = fma2(w2pre[gg * HH + h], s2[h], accv);
        t2[gg] = accv;
    }

    // Row max
    float lmax[HH];
#pragma unroll
    for (int gg = 0; gg < HH; gg++) {
        float lo, hi; upk2(t2[gg], lo, hi);
        lmax[gg] = v1 ? fmaxf(lo, hi) : lo;
    }
#pragma unroll
    for (int gg = 0; gg < HH; gg++)
#pragma unroll
        for (int o = 16; o > 0; o >>= 1)
            lmax[gg] = fmaxf(lmax[gg], __shfl_xor_sync(0xffffffffu, lmax[gg], o));
    if (lane == 0)
#pragma unroll
        for (int gg = 0; gg < HH; gg++) red[warp][gg] = lmax[gg];
    __syncthreads();
    if (tid < HH) {
        float mx = red[0][tid];
#pragma unroll
        for (int w = 1; w < MIXT / 32; w++) mx = fmaxf(mx, red[w][tid]);
        smax[tid] = mx;
    }
    __syncthreads();

    // exp + row sum
    float lsum[HH];
#pragma unroll
    for (int gg = 0; gg < HH; gg++) {
        float lo, hi; upk2(t2[gg], lo, hi);
        float el = __expf(lo - smax[gg]);
        float eh = v1 ? __expf(hi - smax[gg]) : 0.f;
        t2[gg] = pk2(el, eh);
        lsum[gg] = el + eh;
    }
#pragma unroll
    for (int gg = 0; gg < HH; gg++)
#pragma unroll
        for (int o = 16; o > 0; o >>= 1)
            lsum[gg] += __shfl_xor_sync(0xffffffffu, lsum[gg], o);
    if (lane == 0)
#pragma unroll
        for (int gg = 0; gg < HH; gg++) red[warp][gg] = lsum[gg];
    __syncthreads();
    if (tid < HH) {
        float s = red[0][tid];
#pragma unroll
        for (int w = 1; w < MIXT / 32; w++) s += red[w][tid];
        sinv[tid] = 1.f / s;
    }
    __syncthreads();

    // normalize
#pragma unroll
    for (int h = 0; h < HH; h++) {
        float iv = sinv[h];
        t2[h] = mul2(t2[h], pk2(iv, iv));
    }

    // Post-mix + store (tf32-rounded)
    float* Pb = P2 + ((long long)b * HH * NTOK + n) * LD_P;
#pragma unroll
    for (int gg = 0; gg < HH; gg++) {
        unsigned long long accv = 0ull;
#pragma unroll
        for (int h = 0; h < HH; h++)
            accv = fma2(w2post[gg * HH + h], t2[h], accv);
        float lo, hi; upk2(accv, lo, hi);
        float* q = Pb + (long long)gg * NTOK * LD_P;
        q[m0] = rndf(lo);
        if (v1)              q[m1] = rndf(hi);
        else if (m1 < LD_P)  q[m1] = 0.f;
    }
}

// ---------------------------------------------------------------------------
// Launch
// ---------------------------------------------------------------------------
extern "C" void kernel_launch(void* const* d_in, const int* in_sizes, int n_in,
                              void* d_out, int out_size)
{
    const float* x     = (const float*)d_in[0];
    const float* Wqkv  = (const float*)d_in[1];
    const float* Wproj = (const float*)d_in[2];
    const float* bproj = (const float*)d_in[3];
    const float* Wpre  = (const float*)d_in[4];
    const float* Wpost = (const float*)d_in[5];
    float* out = (float*)d_out;

    float *qkv, *S, *P2, *vT, *tmp, *xr, *wqkvr, *wprojr;
    cudaGetSymbolAddress((void**)&qkv, g_qkv);
    cudaGetSymbolAddress((void**)&S,   g_S);
    cudaGetSymbolAddress((void**)&P2,  g_P2);
    cudaGetSymbolAddress((void**)&vT,  g_vT);
    cudaGetSymbolAddress((void**)&tmp, g_tmp);
    cudaGetSymbolAddress((void**)&xr,  g_xr);
    cudaGetSymbolAddress((void**)&wqkvr, g_wqkvr);
    cudaGetSymbolAddress((void**)&wprojr, g_wprojr);

    // 0) tf32-round raw inputs
    round_copy_kernel<<<512, 256>>>(x, xr, MROW * CH / 4);
    round_copy_kernel<<<256, 256>>>(Wqkv, wqkvr, C3 * CH / 4);
    round_copy_kernel<<<128, 256>>>(Wproj, wprojr, CH * CH / 4);

    const int smem_128 = 2 * (128 + 128) * 36 * 4;   // 73728
    const int smem_av  = 2 * (128 + 64) * 36 * 4;    // 55296
    cudaFuncSetAttribute(tc_gemm_nt<128, 128, true>,
                         cudaFuncAttributeMaxDynamicSharedMemorySize, smem_128);
    cudaFuncSetAttribute(tc_gemm_nt<128, 128, false>,
                         cudaFuncAttributeMaxDynamicSharedMemorySize, smem_128);
    cudaFuncSetAttribute(tc_gemm_nt<128, 64, true>,
                         cudaFuncAttributeMaxDynamicSharedMemorySize, smem_av);

    // 1) QKV GEMM: qkv = round(xr @ Wqkv^T)   [9232 x 2304], K=768
    {
        dim3 grid(C3 / 128, (MROW + 127) / 128, 1);
        tc_gemm_nt<128, 128, true><<<grid, 256, smem_128>>>(
            xr, wqkvr, qkv, nullptr,
            MROW, C3, CH, CH, CH, C3, 1.0f,
            1, 0, 0, 0, 0, 0, 0);
    }

    // 1.5) Transpose V -> vT[b,h,d,m]
    {
        dim3 grid(2, (NTOK + 31) / 32, NBH);
        transpose_v_kernel<<<grid, 256>>>(qkv, vT);
    }

    // 2) Scores: S = 1/8 * q @ k^T   (batched 192, M=N=577, K=64)
    {
        dim3 grid((NTOK + 127) / 128, (NTOK + 127) / 128, NBH);
        tc_gemm_nt<128, 128, false><<<grid, 256, smem_128>>>(
            qkv, qkv + CH, S, nullptr,
            NTOK, NTOK, DD,
            C3, C3, LD_S, 0.125f,
            HH,
            (long long)NTOK * C3, DD,
            (long long)NTOK * C3, DD,
            (long long)HH * NTOK * LD_S, (long long)NTOK * LD_S);
    }

    // 3) Fused Wpre-mix -> softmax -> Wpost-mix (register/f32x2 version)
    mix_softmax_kernel<<<MROW, MIXT>>>(S, Wpre, Wpost, P2);

    // 4) AV: tmp = round(P2 @ vT^T)   (K padded to 608)
    {
        dim3 grid(1, (NTOK + 127) / 128, NBH);
        tc_gemm_nt<128, 64, true><<<grid, 256, smem_av>>>(
            P2, vT, tmp, nullptr,
            NTOK, DD, LD_P,
            LD_P, LD_P, CH, 1.0f,
            HH,
            (long long)HH * NTOK * LD_P, (long long)NTOK * LD_P,
            (long long)HH * DD * LD_P,   (long long)DD * LD_P,
            (long long)NTOK * CH,        DD);
    }

    // 5) Projection: out = tmp @ Wproj^T + bproj   [9232 x 768], K=768
    {
        dim3 grid(CH / 128, (MROW + 127) / 128, 1);
        tc_gemm_nt<128, 128, false><<<grid, 256, smem_128>>>(
            tmp, wprojr, out, bproj,
            MROW, CH, CH, CH, CH, CH, 1.0f,
            1, 0, 0, 0, 0, 0, 0);
    }
}